// round 11
// baseline (speedup 1.0000x reference)
#include <cuda_runtime.h>
#include <cuda_bf16.h>
#include <stdint.h>

#define WS 7
#define DROP_PROB 0.1f
#define H 256
#define W 256
#define HC (H - WS + 1)   // 250
#define WC (W - WS + 1)   // 250
#define BC (16 * 64)      // batch * channels = 1024
#define N4 (BC * H * W / 4)          // 16,777,216 float4 total
#define WORDS_PER_ROW 8              // 256 cols / 32 bits

#define BLOCKS 2048
#define THREADS 256
#define STRIDE (BLOCKS * THREADS)    // 524,288 — multiple of 16384
#define KITERS (N4 / STRIDE)         // 32
#define BATCH 4                      // loads in flight per batch

// ---------------------------------------------------------------------------
// Fused persistent kernel, v3. Same mask mechanism as R9/R10 (per-block
// iteration-invariant 4-row window, ballots + 64-bit bit-smear), but with
// 8x fewer blocks and 8x more streaming iterations per block, so the mask
// prologue (L2 u reads, ballots, 2x syncthreads, nibble reduce) is amortized
// over 32 iterations instead of 4 (~10% -> ~1% of block lifetime).
// Streaming body: batches of 4 independent LDG.128 then 4 FMUL+STG.128.
// ---------------------------------------------------------------------------
__global__ void __launch_bounds__(THREADS) fused_dropout_kernel(
        const float4* __restrict__ x, float4* __restrict__ out,
        const float* __restrict__ u) {
    __shared__ uint32_t hd[10][WORDS_PER_ROW];   // dilated anchor rows

    int tid  = threadIdx.x;
    int lane = tid & 31;
    int warp = tid >> 5;

    int base = blockIdx.x * THREADS;             // 256-aligned
    int L    = base & (H * W / 4 - 1);           // local float4 window start
    int r0   = L >> 6;                           // first of 4 pixel rows

    int a_start = r0 - (WS - 1); if (a_start < 0) a_start = 0;
    int a_end   = r0 + 3;        if (a_end > HC - 1) a_end = HC - 1;
    int nrows   = a_end - a_start + 1;           // <= 10

    // Phase 1: ballots + horizontal smear. Warp w covers relative rows w, w+8.
    #pragma unroll
    for (int pass = 0; pass < 2; ++pass) {
        int rr = warp + (pass << 3);             // 0..7, 8..15
        if (rr < nrows) {
            const float* __restrict__ urow = u + (a_start + rr) * WC;
            uint32_t dec[WORDS_PER_ROW];
            #pragma unroll
            for (int w = 0; w < WORDS_PER_ROW; ++w) {
                int col = (w << 5) + lane;
                bool pred = (col < WC) && (urow[col] < DROP_PROB);
                dec[w] = __ballot_sync(0xFFFFFFFFu, pred);  // uniform in warp
            }
            if (lane < WORDS_PER_ROW) {
                uint32_t hi = dec[0], lo = 0u;
                #pragma unroll
                for (int w = 0; w < WORDS_PER_ROW; ++w)
                    if (lane == w) { hi = dec[w]; lo = (w == 0) ? 0u : dec[w - 1]; }
                uint64_t v = ((uint64_t)hi << 32) | (uint64_t)lo;
                v |= v << 1;   // smear left by 6 total:
                v |= v << 2;   //   1+2+3 covers shifts 0..6
                v |= v << 3;
                hd[rr][lane] = (uint32_t)(v >> 32);
            }
        }
    }
    __syncthreads();

    // Phase 2: per-thread nibble -> float4 multiplier (computed ONCE).
    int row  = r0 + (tid >> 6);                  // this thread's pixel row
    int colw = tid & 63;                         // float4 column 0..63
    int wa0  = row - (WS - 1); if (wa0 < a_start) wa0 = a_start;
    int wa1  = row;            if (wa1 > a_end)   wa1 = a_end;
    uint32_t word = 0;
    for (int a = wa0; a <= wa1; ++a)
        word |= hd[a - a_start][colw >> 3];
    uint32_t nib = (word >> ((colw & 7) << 2)) & 0xFu;

    float4 m;
    m.x = (nib & 1u) ? 0.0f : 1.0f;
    m.y = (nib & 2u) ? 0.0f : 1.0f;
    m.z = (nib & 4u) ? 0.0f : 1.0f;
    m.w = (nib & 8u) ? 0.0f : 1.0f;

    // Phase 3: persistent stream — 32 iterations in batches of 4.
    int i0 = base + tid;
    #pragma unroll
    for (int g = 0; g < KITERS; g += BATCH) {
        float4 xv[BATCH];
        #pragma unroll
        for (int k = 0; k < BATCH; ++k)
            xv[k] = x[i0 + (g + k) * STRIDE];
        #pragma unroll
        for (int k = 0; k < BATCH; ++k) {
            float4 ov;
            ov.x = xv[k].x * m.x;
            ov.y = xv[k].y * m.y;
            ov.z = xv[k].z * m.z;
            ov.w = xv[k].w * m.w;
            out[i0 + (g + k) * STRIDE] = ov;
        }
    }
}

extern "C" void kernel_launch(void* const* d_in, const int* in_sizes, int n_in,
                              void* d_out, int out_size) {
    const float* x = (const float*)d_in[0];   // [16, 64, 256, 256] fp32
    const float* u = (const float*)d_in[1];   // [250, 250] fp32
    float* out = (float*)d_out;

    fused_dropout_kernel<<<BLOCKS, THREADS>>>(
        reinterpret_cast<const float4*>(x),
        reinterpret_cast<float4*>(out), u);
}

// round 13
// speedup vs baseline: 1.0677x; 1.0677x over previous
#include <cuda_runtime.h>
#include <cuda_bf16.h>
#include <stdint.h>

#define WS 7
#define DROP_PROB 0.1f
#define H 256
#define W 256
#define HC (H - WS + 1)   // 250
#define WC (W - WS + 1)   // 250
#define BC (16 * 64)      // batch * channels = 1024
#define N8 (BC * H * W / 8)          // 8,388,608 float8 total
#define IMG8 (H * W / 8)             // 8192 float8 per image
#define WORDS_PER_ROW 8              // 256 cols / 32 bits

#define BLOCKS 8192
#define THREADS 256
#define STRIDE (BLOCKS * THREADS)    // 2,097,152 — multiple of IMG8 (8192)
#define KITERS (N8 / STRIDE)         // 4

// ---------------------------------------------------------------------------
// Fused kernel, v4: 256-bit loads/stores (ld/st.global.v8.b32, sm_100a).
// Each thread handles one float8 per iteration; stride is a multiple of the
// per-image float8 count, so each block touches ONE 256-float8 local window
// = 8 consecutive image rows, invariant across all KITERS iterations.
// Mask build: ballots + 64-bit horizontal smear over <=14 anchor rows.
// Per-thread: 8-bit mask byte -> 8 float multipliers, computed once.
// ---------------------------------------------------------------------------
__global__ void __launch_bounds__(THREADS) fused_dropout_kernel(
        const float* __restrict__ x, float* __restrict__ out,
        const float* __restrict__ u) {
    __shared__ uint32_t hd[14][WORDS_PER_ROW];   // dilated anchor rows

    int tid  = threadIdx.x;
    int lane = tid & 31;
    int warp = tid >> 5;

    int base = blockIdx.x * THREADS;             // 256-aligned float8 index
    int L    = base & (IMG8 - 1);                // local float8 window start
    int r0   = L >> 5;                           // first of 8 pixel rows

    int a_start = r0 - (WS - 1); if (a_start < 0) a_start = 0;
    int a_end   = r0 + 7;        if (a_end > HC - 1) a_end = HC - 1;
    int nrows   = a_end - a_start + 1;           // <= 14

    // Phase 1: ballots + horizontal smear. Warp w covers relative rows w, w+8.
    #pragma unroll
    for (int pass = 0; pass < 2; ++pass) {
        int rr = warp + (pass << 3);             // 0..7, 8..15
        if (rr < nrows) {
            const float* __restrict__ urow = u + (a_start + rr) * WC;
            uint32_t dec[WORDS_PER_ROW];
            #pragma unroll
            for (int w = 0; w < WORDS_PER_ROW; ++w) {
                int col = (w << 5) + lane;
                bool pred = (col < WC) && (urow[col] < DROP_PROB);
                dec[w] = __ballot_sync(0xFFFFFFFFu, pred);  // uniform in warp
            }
            if (lane < WORDS_PER_ROW) {
                uint32_t hi = dec[0], lo = 0u;
                #pragma unroll
                for (int w = 0; w < WORDS_PER_ROW; ++w)
                    if (lane == w) { hi = dec[w]; lo = (w == 0) ? 0u : dec[w - 1]; }
                uint64_t v = ((uint64_t)hi << 32) | (uint64_t)lo;
                v |= v << 1;   // smear left by 6 total:
                v |= v << 2;   //   1+2+3 covers shifts 0..6
                v |= v << 3;
                hd[rr][lane] = (uint32_t)(v >> 32);
            }
        }
    }
    __syncthreads();

    // Phase 2: per-thread mask byte -> 8 float multipliers (computed ONCE).
    int row  = r0 + (tid >> 5);                  // this thread's pixel row
    int col8 = tid & 31;                         // float8 column 0..31
    int wa0  = row - (WS - 1); if (wa0 < a_start) wa0 = a_start;
    int wa1  = row;            if (wa1 > a_end)   wa1 = a_end;
    uint32_t word = 0;
    for (int a = wa0; a <= wa1; ++a)
        word |= hd[a - a_start][col8 >> 2];
    uint32_t byte = (word >> ((col8 & 3) << 3)) & 0xFFu;

    float m[8];
    #pragma unroll
    for (int j = 0; j < 8; ++j)
        m[j] = (byte & (1u << j)) ? 0.0f : 1.0f;

    // Phase 3: stream KITERS float8 with 256-bit ld/st.
    #pragma unroll
    for (int k = 0; k < KITERS; ++k) {
        long long i = (long long)(base + tid) + (long long)k * STRIDE;
        const float* px = x + i * 8;
        float*       po = out + i * 8;
        uint32_t r0_, r1_, r2_, r3_, r4_, r5_, r6_, r7_;
        asm volatile(
            "ld.global.nc.v8.b32 {%0,%1,%2,%3,%4,%5,%6,%7}, [%8];"
            : "=r"(r0_), "=r"(r1_), "=r"(r2_), "=r"(r3_),
              "=r"(r4_), "=r"(r5_), "=r"(r6_), "=r"(r7_)
            : "l"(px));
        float v0 = __uint_as_float(r0_) * m[0];
        float v1 = __uint_as_float(r1_) * m[1];
        float v2 = __uint_as_float(r2_) * m[2];
        float v3 = __uint_as_float(r3_) * m[3];
        float v4 = __uint_as_float(r4_) * m[4];
        float v5 = __uint_as_float(r5_) * m[5];
        float v6 = __uint_as_float(r6_) * m[6];
        float v7 = __uint_as_float(r7_) * m[7];
        asm volatile(
            "st.global.v8.b32 [%0], {%1,%2,%3,%4,%5,%6,%7,%8};"
            :: "l"(po),
               "r"(__float_as_uint(v0)), "r"(__float_as_uint(v1)),
               "r"(__float_as_uint(v2)), "r"(__float_as_uint(v3)),
               "r"(__float_as_uint(v4)), "r"(__float_as_uint(v5)),
               "r"(__float_as_uint(v6)), "r"(__float_as_uint(v7))
            : "memory");
    }
}

extern "C" void kernel_launch(void* const* d_in, const int* in_sizes, int n_in,
                              void* d_out, int out_size) {
    const float* x = (const float*)d_in[0];   // [16, 64, 256, 256] fp32
    const float* u = (const float*)d_in[1];   // [250, 250] fp32
    float* out = (float*)d_out;

    fused_dropout_kernel<<<BLOCKS, THREADS>>>(x, out, u);
}